// round 9
// baseline (speedup 1.0000x reference)
#include <cuda_runtime.h>
#include <cuda_bf16.h>
#include <math.h>

#define B     32
#define HID   4096
#define NH    32
#define NKV   8
#define HS    128
#define BSZ   16
#define MAXS  2048
#define MAXB  128
#define G     4
#define QKVN  (HID + 2*NKV*HS)   /* 6144 */
#define SPLIT 8
#define CHUNK 256
#define TS    32
#define KSQ   3                   /* k-split for qkv gemm  (48*3 = 144 blocks) */
#define KSO   4                   /* k-split for out gemm  (32*4 = 128 blocks) */
#define KCHUNK_Q 1376             /* 1376,1376,1344 — all multiples of 32 */

#define SCALE 0.08838834764831845f   /* 128^-0.5 */

__device__ float g_gp[KSQ][B][QKVN];         // GEMM k-split partials (>= KSO*B*HID floats, reused by out-proj)
__device__ float g_qkv[B][QKVN];             // q | k | v
__device__ float g_attn[B][HID];             // attention output (pre O-proj)
__device__ float g_pm[B*NKV*G*SPLIT];        // split-KV partial max
__device__ float g_pl[B*NKV*G*SPLIT];        // split-KV partial sum
__device__ float g_pacc[B*NKV*G*SPLIT][HS];  // split-KV partial acc

// ---------- packed fp32x2 helpers (FFMA2: 2x fp32 MAC rate on sm_103a) ----------
__device__ __forceinline__ void ffma2(unsigned long long &acc, unsigned long long a, unsigned long long b){
    asm("fma.rn.f32x2 %0, %1, %2, %0;" : "+l"(acc) : "l"(a), "l"(b));
}
__device__ __forceinline__ unsigned long long dup2(float x){
    unsigned long long r; asm("mov.b64 %0, {%1, %1};" : "=l"(r) : "f"(x)); return r;
}
__device__ __forceinline__ float2 unpk(unsigned long long v){
    float2 r; asm("mov.b64 {%0, %1}, %2;" : "=f"(r.x), "=f"(r.y) : "l"(v)); return r;
}

// ---------- skinny GEMM tile: Y[0:32, n0:n0+128] over K slice [k0, k0+kb) ----------
// X: [32, K] row-major.  W: rows of length K (row wrow0+n).  Y row stride ldY.
// Thread (tx=tid&15, ty=tid>>4): 2 m-rows (2ty,2ty+1) x 8 n-cols (8tx..8tx+7).
// Per k: 3x LDS.128 + 8x FFMA2 (xs stores x pre-duplicated as {v,v} pairs).
__device__ __forceinline__ void gemm_tile(const float* __restrict__ X, const float* __restrict__ W,
                                          float* __restrict__ Y, int K, int ldY, int n0, int wrow0,
                                          int k0, int kb)
{
    __shared__ unsigned long long xs[32][36];  // [k][m] dup-pairs {v,v}; rows 288B (16B-aligned)
    __shared__ float ws[32][132];              // [k][n] transposed W tile; rows 528B (16B-aligned)

    const int tid = threadIdx.x;
    const int tx = tid & 15;
    const int ty = tid >> 4;

    unsigned long long a00=0, a01=0, a02=0, a03=0;
    unsigned long long a10=0, a11=0, a12=0, a13=0;

    const int lm = tid >> 3, lc = tid & 7;   // X loader: row lm (0..31), float4 col lc (0..7)
    const int wn = tid >> 1, wq = tid & 1;   // W loader: n-row wn (0..127), half wq
    const float* Xp = X + (size_t)lm*K + k0 + 4*lc;
    const float* Wp = W + (size_t)(wrow0 + wn)*K + k0;

    for (int kt = 0; kt < kb; kt += 32) {
        float4 xv = *(const float4*)(Xp + kt);
        xs[4*lc+0][lm] = dup2(xv.x); xs[4*lc+1][lm] = dup2(xv.y);
        xs[4*lc+2][lm] = dup2(xv.z); xs[4*lc+3][lm] = dup2(xv.w);
        #pragma unroll
        for (int i = 0; i < 4; i++) {
            int c4 = wq*4 + i;                       // float4 index within 32-k slice
            float4 wv = *(const float4*)(Wp + kt + 4*c4);
            ws[4*c4+0][wn] = wv.x; ws[4*c4+1][wn] = wv.y;
            ws[4*c4+2][wn] = wv.z; ws[4*c4+3][wn] = wv.w;
        }
        __syncthreads();
        #pragma unroll
        for (int k = 0; k < 32; k++) {
            ulonglong2 w01 = *(const ulonglong2*)&ws[k][8*tx];     // cols 8tx..8tx+3
            ulonglong2 w23 = *(const ulonglong2*)&ws[k][8*tx+4];   // cols 8tx+4..8tx+7
            ulonglong2 bv  = *(const ulonglong2*)&xs[k][2*ty];     // {x0,x0},{x1,x1}
            ffma2(a00, w01.x, bv.x); ffma2(a01, w01.y, bv.x);
            ffma2(a02, w23.x, bv.x); ffma2(a03, w23.y, bv.x);
            ffma2(a10, w01.x, bv.y); ffma2(a11, w01.y, bv.y);
            ffma2(a12, w23.x, bv.y); ffma2(a13, w23.y, bv.y);
        }
        __syncthreads();
    }
    {
        float2 r0 = unpk(a00), r1 = unpk(a01), r2 = unpk(a02), r3 = unpk(a03);
        float* yp = Y + (size_t)(2*ty+0)*ldY + n0 + 8*tx;
        *(float4*)yp     = make_float4(r0.x, r0.y, r1.x, r1.y);
        *(float4*)(yp+4) = make_float4(r2.x, r2.y, r3.x, r3.y);
    }
    {
        float2 r0 = unpk(a10), r1 = unpk(a11), r2 = unpk(a12), r3 = unpk(a13);
        float* yp = Y + (size_t)(2*ty+1)*ldY + n0 + 8*tx;
        *(float4*)yp     = make_float4(r0.x, r0.y, r1.x, r1.y);
        *(float4*)(yp+4) = make_float4(r2.x, r2.y, r3.x, r3.y);
    }
}

__global__ void __launch_bounds__(256) qkv_gemm(const float* __restrict__ x,
                                                const float* __restrict__ wq,
                                                const float* __restrict__ wk,
                                                const float* __restrict__ wv)
{
    int n0 = blockIdx.x * 128;                 // 48 n-tiles; none cross the q/k/v boundaries
    const float* W; int wr;
    if (n0 < HID)                 { W = wq; wr = n0; }
    else if (n0 < HID + NKV*HS)   { W = wk; wr = n0 - HID; }
    else                          { W = wv; wr = n0 - HID - NKV*HS; }
    int k0 = blockIdx.y * KCHUNK_Q;
    int kb = min(KCHUNK_Q, HID - k0);          // 1376,1376,1344
    gemm_tile(x, W, &g_gp[blockIdx.y][0][0], HID, QKVN, n0, wr, k0, kb);
}

__global__ void __launch_bounds__(256) out_gemm(const float* __restrict__ wo)
{
    int n0 = blockIdx.x * 128;                 // 32 n-tiles
    int k0 = blockIdx.y * (HID / KSO);         // kb = 1024
    gemm_tile(&g_attn[0][0], wo, &g_gp[0][0][0] + (size_t)blockIdx.y * (B*HID), HID, HID,
              n0, n0, k0, HID / KSO);
}

__global__ void __launch_bounds__(256) reduce_qkv()
{
    int i = blockIdx.x * 256 + threadIdx.x;
    if (i < B*QKVN) {
        const float* p = &g_gp[0][0][0];
        const int S = B*QKVN;
        (&g_qkv[0][0])[i] = p[i] + p[i + S] + p[i + 2*S];
    }
}

__global__ void __launch_bounds__(256) reduce_out(float* __restrict__ out)
{
    int i = blockIdx.x * 256 + threadIdx.x;
    if (i < B*HID) {
        const float* p = &g_gp[0][0][0];
        const int S = B*HID;
        out[i] = (p[i] + p[i + S]) + (p[i + 2*S] + p[i + 3*S]);
    }
}

// ---------- split-KV flash-decoding attention ----------
// grid (NKV, SPLIT, B), 128 threads; warp g handles query group g.
__global__ void __launch_bounds__(128) attn_kernel(const float* __restrict__ kc,
                                                   const float* __restrict__ vc,
                                                   const int* __restrict__ bt,
                                                   const int* __restrict__ lens)
{
    const int kv = blockIdx.x, chunk = blockIdx.y, b = blockIdx.z;
    const int tid = threadIdx.x;
    const int lane = tid & 31;
    const int g = tid >> 5;

    const int len  = lens[b];
    const int last = len - 1;
    const int pidx = ((b*NKV + kv)*G + g)*SPLIT + chunk;
    const int c0 = chunk * CHUNK;

    if (c0 >= len) {                 // inactive chunk: neutral partial
        if (lane == 0) { g_pm[pidx] = -INFINITY; g_pl[pidx] = 0.f; }
        float4 z = make_float4(0.f, 0.f, 0.f, 0.f);
        *(float4*)&g_pacc[pidx][4*lane] = z;
        return;
    }

    __shared__ float qs[G][HS];
    __shared__ float knew[HS], vnew[HS];
    __shared__ float ks[TS][HS+4], vs[TS][HS+4];

    const float pos = (float)last;

    // RoPE(q)*scale into smem (lane owns dims {lane, lane+32} and partners +64)
    {
        const float* qp = &g_qkv[b][(kv*G + g)*HS];
        #pragma unroll
        for (int j = 0; j < 2; j++) {
            int d0 = lane + 32*j;
            float x1 = qp[d0], x2 = qp[d0+64];
            float inv = powf(10000.0f, -(float)d0 * (1.0f/64.0f));
            float f = pos * inv, s, c;
            sincosf(f, &s, &c);
            qs[g][d0]    = (x1*c - x2*s) * SCALE;
            qs[g][d0+64] = (x2*c + x1*s) * SCALE;
        }
    }
    if (g == 0) {   // fresh (roped) k and fresh v for the new token
        const float* kp = &g_qkv[b][HID + kv*HS];
        const float* vp = &g_qkv[b][HID + NKV*HS + kv*HS];
        #pragma unroll
        for (int j = 0; j < 2; j++) {
            int d0 = lane + 32*j;
            float x1 = kp[d0], x2 = kp[d0+64];
            float inv = powf(10000.0f, -(float)d0 * (1.0f/64.0f));
            float f = pos * inv, s, c;
            sincosf(f, &s, &c);
            knew[d0]    = x1*c - x2*s;
            knew[d0+64] = x2*c + x1*s;
            vnew[d0]    = vp[d0];
            vnew[d0+64] = vp[d0+64];
        }
    }
    __syncthreads();

    const int cend      = min(c0 + CHUNK, len);
    const int cache_end = min(cend, last);      // s == last comes from fresh k/v, not cache
    float m = -INFINITY, l = 0.f;
    float4 acc = make_float4(0.f, 0.f, 0.f, 0.f);
    const int* btb = bt + b*MAXB;

    for (int t0 = c0; t0 < cache_end; t0 += TS) {
        int nt = min(TS, cache_end - t0);
        {   // stage K/V tile: 4 threads per row, 32 cols each
            int r = tid >> 2, q4 = tid & 3;
            if (r < nt) {
                int s = t0 + r;
                int row = btb[s >> 4]*BSZ + (s & 15);
                const float* kr = kc + ((size_t)row*NKV + kv)*HS + q4*32;
                const float* vr = vc + ((size_t)row*NKV + kv)*HS + q4*32;
                #pragma unroll
                for (int i = 0; i < 8; i++) {
                    *(float4*)&ks[r][q4*32 + 4*i] = *(const float4*)&kr[4*i];
                    *(float4*)&vs[r][q4*32 + 4*i] = *(const float4*)&vr[4*i];
                }
            }
        }
        __syncthreads();

        // each lane owns one position
        float sc = -INFINITY;
        if (lane < nt) {
            const float4* kr4 = (const float4*)&ks[lane][0];
            const float4* qp4 = (const float4*)&qs[g][0];
            float a0 = 0.f;
            #pragma unroll
            for (int i = 0; i < 32; i++) {
                float4 kk = kr4[i], qq = qp4[i];
                a0 += kk.x*qq.x + kk.y*qq.y + kk.z*qq.z + kk.w*qq.w;
            }
            sc = a0;
        }
        float tm = sc;
        #pragma unroll
        for (int o = 16; o; o >>= 1) tm = fmaxf(tm, __shfl_xor_sync(0xffffffffu, tm, o));
        float nm = fmaxf(m, tm);
        float corr = __expf(m - nm);
        float p = (lane < nt) ? __expf(sc - nm) : 0.f;
        float ps = p;
        #pragma unroll
        for (int o = 16; o; o >>= 1) ps += __shfl_xor_sync(0xffffffffu, ps, o);
        l = l*corr + ps;
        m = nm;
        acc.x *= corr; acc.y *= corr; acc.z *= corr; acc.w *= corr;

        #pragma unroll 4
        for (int r = 0; r < nt; r++) {
            float pr = __shfl_sync(0xffffffffu, p, r);
            float4 vv = *(const float4*)&vs[r][4*lane];
            acc.x += pr*vv.x; acc.y += pr*vv.y; acc.z += pr*vv.z; acc.w += pr*vv.w;
        }
        __syncthreads();
    }

    // append the freshly-written token if it falls in this chunk
    if (last >= c0 && last < cend) {
        const float4* kn4 = (const float4*)knew;
        const float4* qp4 = (const float4*)&qs[g][0];
        float sc = 0.f;
        #pragma unroll
        for (int i = 0; i < 32; i++) {
            float4 kk = kn4[i], qq = qp4[i];
            sc += kk.x*qq.x + kk.y*qq.y + kk.z*qq.z + kk.w*qq.w;
        }
        float nm = fmaxf(m, sc);
        float corr = __expf(m - nm);
        float p = __expf(sc - nm);
        l = l*corr + p;
        m = nm;
        acc.x *= corr; acc.y *= corr; acc.z *= corr; acc.w *= corr;
        float4 vv = *(const float4*)&vnew[4*lane];
        acc.x += p*vv.x; acc.y += p*vv.y; acc.z += p*vv.z; acc.w += p*vv.w;
    }

    if (lane == 0) { g_pm[pidx] = m; g_pl[pidx] = l; }
    *(float4*)&g_pacc[pidx][4*lane] = acc;
}

// ---------- combine split-KV partials ----------
__global__ void __launch_bounds__(128) combine_kernel()
{
    const int kv = blockIdx.x, b = blockIdx.y;
    const int tid = threadIdx.x, lane = tid & 31, g = tid >> 5;
    const int p0 = ((b*NKV + kv)*G + g)*SPLIT;

    float M = -INFINITY;
    #pragma unroll
    for (int c = 0; c < SPLIT; c++) M = fmaxf(M, g_pm[p0 + c]);

    float L = 0.f;
    float4 o = make_float4(0.f, 0.f, 0.f, 0.f);
    #pragma unroll
    for (int c = 0; c < SPLIT; c++) {
        float pm = g_pm[p0 + c];
        float w = (pm == -INFINITY) ? 0.f : __expf(pm - M);
        L += g_pl[p0 + c] * w;
        float4 a = *(const float4*)&g_pacc[p0 + c][4*lane];
        o.x += a.x*w; o.y += a.y*w; o.z += a.z*w; o.w += a.w*w;
    }
    float inv = 1.0f / L;
    float4 r = make_float4(o.x*inv, o.y*inv, o.z*inv, o.w*inv);
    *(float4*)&g_attn[b][(kv*G + g)*HS + 4*lane] = r;
}

extern "C" void kernel_launch(void* const* d_in, const int* in_sizes, int n_in,
                              void* d_out, int out_size)
{
    const float* hs   = (const float*)d_in[0];
    const float* wq   = (const float*)d_in[1];
    const float* wk   = (const float*)d_in[2];
    const float* wv   = (const float*)d_in[3];
    const float* wo   = (const float*)d_in[4];
    const float* kc   = (const float*)d_in[5];
    const float* vc   = (const float*)d_in[6];
    const int*   bt   = (const int*)d_in[8];
    const int*   lens = (const int*)d_in[10];
    float* out = (float*)d_out;

    qkv_gemm<<<dim3(QKVN/128, KSQ), 256>>>(hs, wq, wk, wv);
    reduce_qkv<<<(B*QKVN + 255)/256, 256>>>();
    attn_kernel<<<dim3(NKV, SPLIT, B), 128>>>(kc, vc, bt, lens);
    combine_kernel<<<dim3(NKV, B), 128>>>();
    out_gemm<<<dim3(HID/128, KSO), 256>>>(wo);
    reduce_out<<<(B*HID + 255)/256, 256>>>(out);
}

// round 10
// speedup vs baseline: 1.2766x; 1.2766x over previous
#include <cuda_runtime.h>
#include <cuda_bf16.h>
#include <math.h>

#define B     32
#define HID   4096
#define NH    32
#define NKV   8
#define HS    128
#define BSZ   16
#define MAXS  2048
#define MAXB  128
#define G     4
#define QKVN  (HID + 2*NKV*HS)   /* 6144 */
#define SPLIT 8
#define CHUNK 256
#define TS    32
#define KSQ   3                   /* k-split for qkv gemm  (48*3 = 144 blocks) */
#define KSO   4                   /* k-split for out gemm  (32*4 = 128 blocks) */
#define KCHUNK_Q 1376             /* 1376,1376,1344 — all multiples of 32 */

#define SCALE 0.08838834764831845f   /* 128^-0.5 */

__device__ float g_gp[KSQ][B][QKVN];         // GEMM k-split partials (>= KSO*B*HID floats, reused by out-proj)
__device__ float g_qkv[B][QKVN];             // q | k | v
__device__ float g_attn[B][HID];             // attention output (pre O-proj)
__device__ float g_pm[B*NKV*G*SPLIT];        // split-KV partial max
__device__ float g_pl[B*NKV*G*SPLIT];        // split-KV partial sum
__device__ float g_pacc[B*NKV*G*SPLIT][HS];  // split-KV partial acc

// ---------- packed fp32x2 helpers (FFMA2: 2x fp32 MAC rate on sm_103a) ----------
__device__ __forceinline__ void ffma2(unsigned long long &acc, unsigned long long a, unsigned long long b){
    asm("fma.rn.f32x2 %0, %1, %2, %0;" : "+l"(acc) : "l"(a), "l"(b));
}
__device__ __forceinline__ unsigned long long mul2(unsigned long long a, unsigned long long b){
    unsigned long long r; asm("mul.rn.f32x2 %0, %1, %2;" : "=l"(r) : "l"(a), "l"(b)); return r;
}
__device__ __forceinline__ unsigned long long dup2(float x){
    unsigned long long r; asm("mov.b64 %0, {%1, %1};" : "=l"(r) : "f"(x)); return r;
}
__device__ __forceinline__ float2 unpk(unsigned long long v){
    float2 r; asm("mov.b64 {%0, %1}, %2;" : "=f"(r.x), "=f"(r.y) : "l"(v)); return r;
}

// ---------- skinny GEMM tile: Y[0:32, n0:n0+128] over K slice [k0, k0+kb) ----------
// Thread (tx=tid&31, ty=tid>>5): 4 m-rows (4ty..) x 4 n-cols (4tx..).
// Per k: 1x conflict-free LDS.128 (w) + 2x broadcast LDS.128 (x dups) + 8x FFMA2.
__device__ __forceinline__ void gemm_tile(const float* __restrict__ X, const float* __restrict__ W,
                                          float* __restrict__ Y, int K, int ldY, int n0, int wrow0,
                                          int k0, int kb)
{
    __shared__ unsigned long long xs[32][36];  // [k][m] dup-pairs {v,v}; rows 288B (16B-aligned)
    __shared__ float ws[32][132];              // [k][n] transposed W tile; rows 528B (16B-aligned)

    const int tid = threadIdx.x;
    const int tx = tid & 31;       // 4 n-cols: 4tx..4tx+3
    const int ty = tid >> 5;       // 4 m-rows: 4ty..4ty+3 (constant per warp -> x reads broadcast)

    unsigned long long a00=0, a01=0, a10=0, a11=0;
    unsigned long long a20=0, a21=0, a30=0, a31=0;

    const int lm = tid >> 3, lc = tid & 7;   // X loader: row lm (0..31), float4 col lc (0..7)
    const int wn = tid >> 1, wq = tid & 1;   // W loader: n-row wn (0..127), half wq
    const float* Xp = X + (size_t)lm*K + k0 + 4*lc;
    const float* Wp = W + (size_t)(wrow0 + wn)*K + k0;

    for (int kt = 0; kt < kb; kt += 32) {
        float4 xv = *(const float4*)(Xp + kt);
        xs[4*lc+0][lm] = dup2(xv.x); xs[4*lc+1][lm] = dup2(xv.y);
        xs[4*lc+2][lm] = dup2(xv.z); xs[4*lc+3][lm] = dup2(xv.w);
        #pragma unroll
        for (int i = 0; i < 4; i++) {
            int c4 = wq*4 + i;                       // float4 index within 32-k slice
            float4 wv = *(const float4*)(Wp + kt + 4*c4);
            ws[4*c4+0][wn] = wv.x; ws[4*c4+1][wn] = wv.y;
            ws[4*c4+2][wn] = wv.z; ws[4*c4+3][wn] = wv.w;
        }
        __syncthreads();
        #pragma unroll
        for (int k = 0; k < 32; k++) {
            ulonglong2 wv  = *(const ulonglong2*)&ws[k][4*tx];     // (w0,w1),(w2,w3)
            ulonglong2 b01 = *(const ulonglong2*)&xs[k][4*ty];     // {x0,x0},{x1,x1}
            ulonglong2 b23 = *(const ulonglong2*)&xs[k][4*ty+2];   // {x2,x2},{x3,x3}
            ffma2(a00, wv.x, b01.x); ffma2(a01, wv.y, b01.x);
            ffma2(a10, wv.x, b01.y); ffma2(a11, wv.y, b01.y);
            ffma2(a20, wv.x, b23.x); ffma2(a21, wv.y, b23.x);
            ffma2(a30, wv.x, b23.y); ffma2(a31, wv.y, b23.y);
        }
        __syncthreads();
    }
    #pragma unroll
    for (int i = 0; i < 4; i++) {
        unsigned long long p0, p1;
        if (i == 0)      { p0 = a00; p1 = a01; }
        else if (i == 1) { p0 = a10; p1 = a11; }
        else if (i == 2) { p0 = a20; p1 = a21; }
        else             { p0 = a30; p1 = a31; }
        float2 r0 = unpk(p0), r1 = unpk(p1);
        float* yp = Y + (size_t)(4*ty + i)*ldY + n0 + 4*tx;
        *(float4*)yp = make_float4(r0.x, r0.y, r1.x, r1.y);
    }
}

__global__ void __launch_bounds__(256) qkv_gemm(const float* __restrict__ x,
                                                const float* __restrict__ wq,
                                                const float* __restrict__ wk,
                                                const float* __restrict__ wv)
{
    int n0 = blockIdx.x * 128;                 // 48 n-tiles; none cross the q/k/v boundaries
    const float* W; int wr;
    if (n0 < HID)                 { W = wq; wr = n0; }
    else if (n0 < HID + NKV*HS)   { W = wk; wr = n0 - HID; }
    else                          { W = wv; wr = n0 - HID - NKV*HS; }
    int k0 = blockIdx.y * KCHUNK_Q;
    int kb = min(KCHUNK_Q, HID - k0);          // 1376,1376,1344
    gemm_tile(x, W, &g_gp[blockIdx.y][0][0], HID, QKVN, n0, wr, k0, kb);
}

__global__ void __launch_bounds__(256) out_gemm(const float* __restrict__ wo)
{
    int n0 = blockIdx.x * 128;                 // 32 n-tiles
    int k0 = blockIdx.y * (HID / KSO);         // kb = 1024
    gemm_tile(&g_attn[0][0], wo, &g_gp[0][0][0] + (size_t)blockIdx.y * (B*HID), HID, HID,
              n0, n0, k0, HID / KSO);
}

__global__ void __launch_bounds__(256) reduce_qkv()
{
    int i = blockIdx.x * 256 + threadIdx.x;
    if (i < B*QKVN) {
        const float* p = &g_gp[0][0][0];
        const int S = B*QKVN;
        (&g_qkv[0][0])[i] = p[i] + p[i + S] + p[i + 2*S];
    }
}

__global__ void __launch_bounds__(256) reduce_out(float* __restrict__ out)
{
    int i = blockIdx.x * 256 + threadIdx.x;
    if (i < B*HID) {
        const float* p = &g_gp[0][0][0];
        const int S = B*HID;
        out[i] = (p[i] + p[i + S]) + (p[i + 2*S] + p[i + 3*S]);
    }
}

// ---------- split-KV flash-decoding attention ----------
// grid (NKV, SPLIT, B), 128 threads; warp g handles query group g.
// K/V tiles stored with XOR quad-swizzle: element (r, c) lives at quad (c>>2)^(r&7).
// All LDS/STS land on the 4-cyc crossbar floor (no bank conflicts).
__global__ void __launch_bounds__(128) attn_kernel(const float* __restrict__ kc,
                                                   const float* __restrict__ vc,
                                                   const int* __restrict__ bt,
                                                   const int* __restrict__ lens)
{
    const int kv = blockIdx.x, chunk = blockIdx.y, b = blockIdx.z;
    const int tid = threadIdx.x;
    const int lane = tid & 31;
    const int g = tid >> 5;

    const int len  = lens[b];
    const int last = len - 1;
    const int pidx = ((b*NKV + kv)*G + g)*SPLIT + chunk;
    const int c0 = chunk * CHUNK;

    if (c0 >= len) {                 // inactive chunk: neutral partial
        if (lane == 0) { g_pm[pidx] = -INFINITY; g_pl[pidx] = 0.f; }
        float4 z = make_float4(0.f, 0.f, 0.f, 0.f);
        *(float4*)&g_pacc[pidx][4*lane] = z;
        return;
    }

    __shared__ float qs[G][HS];
    __shared__ float knew[HS], vnew[HS];
    __shared__ float ks[TS][HS], vs[TS][HS];   // swizzled; rows exactly 512B

    const float pos = (float)last;

    // RoPE(q)*scale into smem (lane owns dims {lane, lane+32} and partners +64)
    {
        const float* qp = &g_qkv[b][(kv*G + g)*HS];
        #pragma unroll
        for (int j = 0; j < 2; j++) {
            int d0 = lane + 32*j;
            float x1 = qp[d0], x2 = qp[d0+64];
            float inv = powf(10000.0f, -(float)d0 * (1.0f/64.0f));
            float f = pos * inv, s, c;
            sincosf(f, &s, &c);
            qs[g][d0]    = (x1*c - x2*s) * SCALE;
            qs[g][d0+64] = (x2*c + x1*s) * SCALE;
        }
    }
    if (g == 0) {   // fresh (roped) k and fresh v for the new token
        const float* kp = &g_qkv[b][HID + kv*HS];
        const float* vp = &g_qkv[b][HID + NKV*HS + kv*HS];
        #pragma unroll
        for (int j = 0; j < 2; j++) {
            int d0 = lane + 32*j;
            float x1 = kp[d0], x2 = kp[d0+64];
            float inv = powf(10000.0f, -(float)d0 * (1.0f/64.0f));
            float f = pos * inv, s, c;
            sincosf(f, &s, &c);
            knew[d0]    = x1*c - x2*s;
            knew[d0+64] = x2*c + x1*s;
            vnew[d0]    = vp[d0];
            vnew[d0+64] = vp[d0+64];
        }
    }
    __syncthreads();

    const int cend      = min(c0 + CHUNK, len);
    const int cache_end = min(cend, last);      // s == last comes from fresh k/v, not cache
    float m = -INFINITY, l = 0.f;
    // packed PV accumulators: lane owns output cols 4*lane..4*lane+3
    unsigned long long a01a=0, a23a=0, a01b=0, a23b=0;
    const int* btb = bt + b*MAXB;
    const int myswz = lane & 7;

    for (int t0 = c0; t0 < cache_end; t0 += TS) {
        int nt = min(TS, cache_end - t0);
        {   // stage K/V tile with quad swizzle: 4 threads per row, 8 quads each
            int r = tid >> 2, q4 = tid & 3;
            if (r < nt) {
                int s = t0 + r;
                int row = btb[s >> 4]*BSZ + (s & 15);
                const float4* kr = (const float4*)(kc + ((size_t)row*NKV + kv)*HS) + q4*8;
                const float4* vr = (const float4*)(vc + ((size_t)row*NKV + kv)*HS) + q4*8;
                int sw = r & 7;
                #pragma unroll
                for (int i = 0; i < 8; i++) {
                    int pq = (q4*8 + i) ^ sw;
                    *(float4*)&ks[r][4*pq] = kr[i];
                    *(float4*)&vs[r][4*pq] = vr[i];
                }
            }
        }
        __syncthreads();

        // QK dot: lane owns one position; 4 packed accumulators (chains of 16)
        float sc = -INFINITY;
        if (lane < nt) {
            const float* kr = &ks[lane][0];
            const ulonglong2* qp2 = (const ulonglong2*)&qs[g][0];
            unsigned long long s0=0, s1=0, s2=0, s3=0;
            #pragma unroll
            for (int i = 0; i < 32; i += 2) {
                ulonglong2 kk0 = *(const ulonglong2*)(kr + 4*(i ^ myswz));
                ulonglong2 qq0 = qp2[i];
                ffma2(s0, kk0.x, qq0.x); ffma2(s1, kk0.y, qq0.y);
                ulonglong2 kk1 = *(const ulonglong2*)(kr + 4*((i+1) ^ myswz));
                ulonglong2 qq1 = qp2[i+1];
                ffma2(s2, kk1.x, qq1.x); ffma2(s3, kk1.y, qq1.y);
            }
            float2 f0 = unpk(s0), f1 = unpk(s1), f2 = unpk(s2), f3 = unpk(s3);
            sc = ((f0.x + f0.y) + (f1.x + f1.y)) + ((f2.x + f2.y) + (f3.x + f3.y));
        }
        float tm = sc;
        #pragma unroll
        for (int o = 16; o; o >>= 1) tm = fmaxf(tm, __shfl_xor_sync(0xffffffffu, tm, o));
        float nm = fmaxf(m, tm);
        float corr = __expf(m - nm);
        float p = (lane < nt) ? __expf(sc - nm) : 0.f;
        float ps = p;
        #pragma unroll
        for (int o = 16; o; o >>= 1) ps += __shfl_xor_sync(0xffffffffu, ps, o);
        l = l*corr + ps;
        m = nm;
        {
            unsigned long long c2 = dup2(corr);
            a01a = mul2(a01a, c2); a23a = mul2(a23a, c2);
            a01b = mul2(a01b, c2); a23b = mul2(a23b, c2);
        }

        #pragma unroll 8
        for (int r = 0; r < nt; r++) {
            float pr = __shfl_sync(0xffffffffu, p, r);
            unsigned long long pd = dup2(pr);
            ulonglong2 vv = *(const ulonglong2*)(&vs[r][0] + 4*(lane ^ (r & 7)));
            if (r & 1) { ffma2(a01b, vv.x, pd); ffma2(a23b, vv.y, pd); }
            else       { ffma2(a01a, vv.x, pd); ffma2(a23a, vv.y, pd); }
        }
        __syncthreads();
    }

    // append the freshly-written token if it falls in this chunk
    if (last >= c0 && last < cend) {
        const float4* kn4 = (const float4*)knew;
        const float4* qp4 = (const float4*)&qs[g][0];
        float sc = 0.f;
        #pragma unroll
        for (int i = 0; i < 32; i++) {
            float4 kk = kn4[i], qq = qp4[i];
            sc += kk.x*qq.x + kk.y*qq.y + kk.z*qq.z + kk.w*qq.w;
        }
        float nm = fmaxf(m, sc);
        float corr = __expf(m - nm);
        float p = __expf(sc - nm);
        l = l*corr + p;
        m = nm;
        unsigned long long c2 = dup2(corr), pd = dup2(p);
        a01a = mul2(a01a, c2); a23a = mul2(a23a, c2);
        a01b = mul2(a01b, c2); a23b = mul2(a23b, c2);
        ulonglong2 vv = *(const ulonglong2*)(vnew + 4*lane);
        ffma2(a01a, vv.x, pd); ffma2(a23a, vv.y, pd);
    }

    if (lane == 0) { g_pm[pidx] = m; g_pl[pidx] = l; }
    {
        float2 xa = unpk(a01a), xb = unpk(a01b), ya = unpk(a23a), yb = unpk(a23b);
        float4 outp = make_float4(xa.x + xb.x, xa.y + xb.y, ya.x + yb.x, ya.y + yb.y);
        *(float4*)&g_pacc[pidx][4*lane] = outp;
    }
}

// ---------- combine split-KV partials ----------
__global__ void __launch_bounds__(128) combine_kernel()
{
    const int kv = blockIdx.x, b = blockIdx.y;
    const int tid = threadIdx.x, lane = tid & 31, g = tid >> 5;
    const int p0 = ((b*NKV + kv)*G + g)*SPLIT;

    float M = -INFINITY;
    #pragma unroll
    for (int c = 0; c < SPLIT; c++) M = fmaxf(M, g_pm[p0 + c]);

    float L = 0.f;
    float4 o = make_float4(0.f, 0.f, 0.f, 0.f);
    #pragma unroll
    for (int c = 0; c < SPLIT; c++) {
        float pm = g_pm[p0 + c];
        float w = (pm == -INFINITY) ? 0.f : __expf(pm - M);
        L += g_pl[p0 + c] * w;
        float4 a = *(const float4*)&g_pacc[p0 + c][4*lane];
        o.x += a.x*w; o.y += a.y*w; o.z += a.z*w; o.w += a.w*w;
    }
    float inv = 1.0f / L;
    float4 r = make_float4(o.x*inv, o.y*inv, o.z*inv, o.w*inv);
    *(float4*)&g_attn[b][(kv*G + g)*HS + 4*lane] = r;
}

extern "C" void kernel_launch(void* const* d_in, const int* in_sizes, int n_in,
                              void* d_out, int out_size)
{
    const float* hs   = (const float*)d_in[0];
    const float* wq   = (const float*)d_in[1];
    const float* wk   = (const float*)d_in[2];
    const float* wv   = (const float*)d_in[3];
    const float* wo   = (const float*)d_in[4];
    const float* kc   = (const float*)d_in[5];
    const float* vc   = (const float*)d_in[6];
    const int*   bt   = (const int*)d_in[8];
    const int*   lens = (const int*)d_in[10];
    float* out = (float*)d_out;

    qkv_gemm<<<dim3(QKVN/128, KSQ), 256>>>(hs, wq, wk, wv);
    reduce_qkv<<<(B*QKVN + 255)/256, 256>>>();
    attn_kernel<<<dim3(NKV, SPLIT, B), 128>>>(kc, vc, bt, lens);
    combine_kernel<<<dim3(NKV, B), 128>>>();
    out_gemm<<<dim3(HID/128, KSO), 256>>>(wo);
    reduce_out<<<(B*HID + 255)/256, 256>>>(out);
}

// round 11
// speedup vs baseline: 1.6219x; 1.2705x over previous
#include <cuda_runtime.h>
#include <cuda_bf16.h>
#include <math.h>

#define B     32
#define HID   4096
#define NH    32
#define NKV   8
#define HS    128
#define BSZ   16
#define MAXS  2048
#define MAXB  128
#define G     4
#define QKVN  (HID + 2*NKV*HS)   /* 6144 */
#define SPLIT 8
#define CHUNK 256
#define TS    16
#define KSQ   3                   /* k-split for qkv gemm  (48*3 = 144 blocks) */
#define KSO   4                   /* k-split for out gemm  (32*4 = 128 blocks) */
#define KCHUNK_Q 1376             /* 1376,1376,1344 — all multiples of 32 */

#define SCALE 0.08838834764831845f   /* 128^-0.5 */

__device__ float g_gp[KSQ][B][QKVN];         // GEMM k-split partials (>= KSO*B*HID floats, reused by out-proj)
__device__ float g_qkv[B][QKVN];             // q | k | v
__device__ float g_attn[B][HID];             // attention output (pre O-proj)
__device__ float g_pm[B*NKV*G*SPLIT];        // split-KV partial max
__device__ float g_pl[B*NKV*G*SPLIT];        // split-KV partial sum
__device__ float g_pacc[B*NKV*G*SPLIT][HS];  // split-KV partial acc

// ---------- packed fp32x2 helpers (FFMA2: 2x fp32 MAC rate on sm_103a) ----------
__device__ __forceinline__ void ffma2(unsigned long long &acc, unsigned long long a, unsigned long long b){
    asm("fma.rn.f32x2 %0, %1, %2, %0;" : "+l"(acc) : "l"(a), "l"(b));
}
__device__ __forceinline__ unsigned long long mul2(unsigned long long a, unsigned long long b){
    unsigned long long r; asm("mul.rn.f32x2 %0, %1, %2;" : "=l"(r) : "l"(a), "l"(b)); return r;
}
__device__ __forceinline__ unsigned long long dup2(float x){
    unsigned long long r; asm("mov.b64 %0, {%1, %1};" : "=l"(r) : "f"(x)); return r;
}
__device__ __forceinline__ float2 unpk(unsigned long long v){
    float2 r; asm("mov.b64 {%0, %1}, %2;" : "=f"(r.x), "=f"(r.y) : "l"(v)); return r;
}
// ---------- cp.async helpers ----------
__device__ __forceinline__ void cpa16(void* s, const void* g){
    unsigned ss = (unsigned)__cvta_generic_to_shared(s);
    asm volatile("cp.async.cg.shared.global [%0], [%1], 16;" :: "r"(ss), "l"(g));
}
#define CPA_COMMIT() asm volatile("cp.async.commit_group;")
#define CPA_WAIT(n)  asm volatile("cp.async.wait_group %0;" :: "n"(n))

// ---------- skinny GEMM tile: Y[0:32, n0:n0+128] over K slice [k0, k0+kb) ----------
// Thread (tx=tid&31, ty=tid>>5): 4 m-rows x 4 n-cols.  Register-prefetched staging.
__device__ __forceinline__ void gemm_tile(const float* __restrict__ X, const float* __restrict__ W,
                                          float* __restrict__ Y, int K, int ldY, int n0, int wrow0,
                                          int k0, int kb)
{
    __shared__ unsigned long long xs[32][36];  // [k][m] dup-pairs {v,v}
    __shared__ float ws[32][132];              // [k][n] transposed W tile

    const int tid = threadIdx.x;
    const int tx = tid & 31;
    const int ty = tid >> 5;

    unsigned long long a00=0, a01=0, a10=0, a11=0;
    unsigned long long a20=0, a21=0, a30=0, a31=0;

    const int lm = tid >> 3, lc = tid & 7;   // X loader
    const int wn = tid >> 1, wq = tid & 1;   // W loader
    const float* Xp = X + (size_t)lm*K + k0 + 4*lc;
    const float* Wp = W + (size_t)(wrow0 + wn)*K + k0;

    float4 xv = *(const float4*)(Xp);
    float4 wv0 = *(const float4*)(Wp + 4*(wq*4+0));
    float4 wv1 = *(const float4*)(Wp + 4*(wq*4+1));
    float4 wv2 = *(const float4*)(Wp + 4*(wq*4+2));
    float4 wv3 = *(const float4*)(Wp + 4*(wq*4+3));

    for (int kt = 0; kt < kb; kt += 32) {
        xs[4*lc+0][lm] = dup2(xv.x); xs[4*lc+1][lm] = dup2(xv.y);
        xs[4*lc+2][lm] = dup2(xv.z); xs[4*lc+3][lm] = dup2(xv.w);
        {
            int c0q = wq*4;
            ws[4*c0q+0][wn]  = wv0.x; ws[4*c0q+1][wn]  = wv0.y; ws[4*c0q+2][wn]  = wv0.z; ws[4*c0q+3][wn]  = wv0.w;
            ws[4*c0q+4][wn]  = wv1.x; ws[4*c0q+5][wn]  = wv1.y; ws[4*c0q+6][wn]  = wv1.z; ws[4*c0q+7][wn]  = wv1.w;
            ws[4*c0q+8][wn]  = wv2.x; ws[4*c0q+9][wn]  = wv2.y; ws[4*c0q+10][wn] = wv2.z; ws[4*c0q+11][wn] = wv2.w;
            ws[4*c0q+12][wn] = wv3.x; ws[4*c0q+13][wn] = wv3.y; ws[4*c0q+14][wn] = wv3.z; ws[4*c0q+15][wn] = wv3.w;
        }
        __syncthreads();
        if (kt + 32 < kb) {       // prefetch next slice while computing this one
            xv  = *(const float4*)(Xp + kt + 32);
            wv0 = *(const float4*)(Wp + kt + 32 + 4*(wq*4+0));
            wv1 = *(const float4*)(Wp + kt + 32 + 4*(wq*4+1));
            wv2 = *(const float4*)(Wp + kt + 32 + 4*(wq*4+2));
            wv3 = *(const float4*)(Wp + kt + 32 + 4*(wq*4+3));
        }
        #pragma unroll
        for (int k = 0; k < 32; k++) {
            ulonglong2 wv  = *(const ulonglong2*)&ws[k][4*tx];
            ulonglong2 b01 = *(const ulonglong2*)&xs[k][4*ty];
            ulonglong2 b23 = *(const ulonglong2*)&xs[k][4*ty+2];
            ffma2(a00, wv.x, b01.x); ffma2(a01, wv.y, b01.x);
            ffma2(a10, wv.x, b01.y); ffma2(a11, wv.y, b01.y);
            ffma2(a20, wv.x, b23.x); ffma2(a21, wv.y, b23.x);
            ffma2(a30, wv.x, b23.y); ffma2(a31, wv.y, b23.y);
        }
        __syncthreads();
    }
    #pragma unroll
    for (int i = 0; i < 4; i++) {
        unsigned long long p0, p1;
        if (i == 0)      { p0 = a00; p1 = a01; }
        else if (i == 1) { p0 = a10; p1 = a11; }
        else if (i == 2) { p0 = a20; p1 = a21; }
        else             { p0 = a30; p1 = a31; }
        float2 r0 = unpk(p0), r1 = unpk(p1);
        float* yp = Y + (size_t)(4*ty + i)*ldY + n0 + 4*tx;
        *(float4*)yp = make_float4(r0.x, r0.y, r1.x, r1.y);
    }
}

__global__ void __launch_bounds__(256) qkv_gemm(const float* __restrict__ x,
                                                const float* __restrict__ wq,
                                                const float* __restrict__ wk,
                                                const float* __restrict__ wv)
{
    int n0 = blockIdx.x * 128;
    const float* W; int wr;
    if (n0 < HID)                 { W = wq; wr = n0; }
    else if (n0 < HID + NKV*HS)   { W = wk; wr = n0 - HID; }
    else                          { W = wv; wr = n0 - HID - NKV*HS; }
    int k0 = blockIdx.y * KCHUNK_Q;
    int kb = min(KCHUNK_Q, HID - k0);
    gemm_tile(x, W, &g_gp[blockIdx.y][0][0], HID, QKVN, n0, wr, k0, kb);
}

__global__ void __launch_bounds__(256) out_gemm(const float* __restrict__ wo)
{
    int n0 = blockIdx.x * 128;
    int k0 = blockIdx.y * (HID / KSO);
    gemm_tile(&g_attn[0][0], wo, &g_gp[0][0][0] + (size_t)blockIdx.y * (B*HID), HID, HID,
              n0, n0, k0, HID / KSO);
}

__global__ void __launch_bounds__(256) reduce_qkv()
{
    int i = blockIdx.x * 256 + threadIdx.x;
    if (i < B*QKVN) {
        const float* p = &g_gp[0][0][0];
        const int S = B*QKVN;
        (&g_qkv[0][0])[i] = p[i] + p[i + S] + p[i + 2*S];
    }
}

__global__ void __launch_bounds__(256) reduce_out(float* __restrict__ out)
{
    int i = blockIdx.x * 256 + threadIdx.x;
    if (i < B*HID) {
        const float* p = &g_gp[0][0][0];
        const int S = B*HID;
        out[i] = (p[i] + p[i + S]) + (p[i + 2*S] + p[i + 3*S]);
    }
}

// ---------- split-KV flash-decoding attention ----------
// grid (NKV, SPLIT, B), 128 threads; warp g handles query group g.
// TS=16 double-buffered cp.async staging, XOR quad-swizzled tiles.
// QK: 2 lanes per position (64 dims each), combined via shfl_xor(16).
__global__ void __launch_bounds__(128) attn_kernel(const float* __restrict__ kc,
                                                   const float* __restrict__ vc,
                                                   const int* __restrict__ bt,
                                                   const int* __restrict__ lens)
{
    const int kv = blockIdx.x, chunk = blockIdx.y, b = blockIdx.z;
    const int tid = threadIdx.x;
    const int lane = tid & 31;
    const int g = tid >> 5;

    const int len  = lens[b];
    const int last = len - 1;
    const int pidx = ((b*NKV + kv)*G + g)*SPLIT + chunk;
    const int c0 = chunk * CHUNK;

    if (c0 >= len) {
        if (lane == 0) { g_pm[pidx] = -INFINITY; g_pl[pidx] = 0.f; }
        float4 z = make_float4(0.f, 0.f, 0.f, 0.f);
        *(float4*)&g_pacc[pidx][4*lane] = z;
        return;
    }

    __shared__ float qs[G][HS];
    __shared__ float knew[HS], vnew[HS];
    __shared__ float ks[2][TS][HS], vs[2][TS][HS];   // double-buffered, swizzled

    const float pos_f = (float)last;

    {   // RoPE(q)*scale
        const float* qp = &g_qkv[b][(kv*G + g)*HS];
        #pragma unroll
        for (int j = 0; j < 2; j++) {
            int d0 = lane + 32*j;
            float x1 = qp[d0], x2 = qp[d0+64];
            float inv = powf(10000.0f, -(float)d0 * (1.0f/64.0f));
            float f = pos_f * inv, s, c;
            sincosf(f, &s, &c);
            qs[g][d0]    = (x1*c - x2*s) * SCALE;
            qs[g][d0+64] = (x2*c + x1*s) * SCALE;
        }
    }
    if (g == 0) {
        const float* kp = &g_qkv[b][HID + kv*HS];
        const float* vp = &g_qkv[b][HID + NKV*HS + kv*HS];
        #pragma unroll
        for (int j = 0; j < 2; j++) {
            int d0 = lane + 32*j;
            float x1 = kp[d0], x2 = kp[d0+64];
            float inv = powf(10000.0f, -(float)d0 * (1.0f/64.0f));
            float f = pos_f * inv, s, c;
            sincosf(f, &s, &c);
            knew[d0]    = x1*c - x2*s;
            knew[d0+64] = x2*c + x1*s;
            vnew[d0]    = vp[d0];
            vnew[d0+64] = vp[d0+64];
        }
    }
    __syncthreads();

    const int cend      = min(c0 + CHUNK, len);
    const int cache_end = min(cend, last);
    const int ntiles    = (cache_end > c0) ? (cache_end - c0 + TS - 1) / TS : 0;

    float m = -INFINITY, l = 0.f;
    unsigned long long a01a=0, a23a=0, a01b=0, a23b=0;   // lane owns cols 4*lane..+3
    const int* btb = bt + b*MAXB;

    const int srow = tid >> 3;          // staging: row 0..15
    const int sq0  = (tid & 7) * 4;     // 4 quads per thread per tensor

    // stage tile i into buffer i&1
    #define STAGE(i) do {                                                        \
        int t0_ = c0 + (i)*TS;                                                   \
        int nt_ = min(TS, cache_end - t0_);                                      \
        int bi_ = (i) & 1;                                                       \
        if (srow < nt_) {                                                        \
            int s_ = t0_ + srow;                                                 \
            int row_ = btb[s_ >> 4]*BSZ + (s_ & 15);                             \
            const float4* kr_ = (const float4*)(kc + ((size_t)row_*NKV + kv)*HS);\
            const float4* vr_ = (const float4*)(vc + ((size_t)row_*NKV + kv)*HS);\
            int sw_ = srow & 7;                                                  \
            _Pragma("unroll")                                                    \
            for (int i2 = 0; i2 < 4; i2++) {                                     \
                int q_ = sq0 + i2; int pq_ = q_ ^ sw_;                           \
                cpa16(&ks[bi_][srow][4*pq_], kr_ + q_);                          \
                cpa16(&vs[bi_][srow][4*pq_], vr_ + q_);                          \
            }                                                                    \
        }                                                                        \
    } while (0)

    if (ntiles > 0) STAGE(0);
    CPA_COMMIT();

    const int pos  = lane & 15;
    const int half = lane >> 4;

    for (int i = 0; i < ntiles; i++) {
        if (i + 1 < ntiles) STAGE(i + 1);
        CPA_COMMIT();
        if (i + 1 < ntiles) CPA_WAIT(1); else CPA_WAIT(0);
        __syncthreads();

        const int bi = i & 1;
        const int t0 = c0 + i*TS;
        const int nt = min(TS, cache_end - t0);

        // QK: lane pair (pos, pos+16) splits the 128-dim dot (quads half*16..half*16+15)
        float sc;
        {
            const float* kr = &ks[bi][pos][0];
            const ulonglong2* qp2 = (const ulonglong2*)&qs[g][0];
            const int swz = pos & 7;
            unsigned long long s0=0, s1=0, s2=0, s3=0;
            #pragma unroll
            for (int q = 0; q < 16; q += 2) {
                int q0 = half*16 + q;
                ulonglong2 kk0 = *(const ulonglong2*)(kr + 4*(q0 ^ swz));
                ulonglong2 qq0 = qp2[q0];
                ffma2(s0, kk0.x, qq0.x); ffma2(s1, kk0.y, qq0.y);
                ulonglong2 kk1 = *(const ulonglong2*)(kr + 4*((q0+1) ^ swz));
                ulonglong2 qq1 = qp2[q0+1];
                ffma2(s2, kk1.x, qq1.x); ffma2(s3, kk1.y, qq1.y);
            }
            float2 f0 = unpk(s0), f1 = unpk(s1), f2 = unpk(s2), f3 = unpk(s3);
            float part = ((f0.x + f0.y) + (f1.x + f1.y)) + ((f2.x + f2.y) + (f3.x + f3.y));
            sc = part + __shfl_xor_sync(0xffffffffu, part, 16);
            if (pos >= nt) sc = -INFINITY;
        }

        float tm = sc;
        #pragma unroll
        for (int o = 8; o; o >>= 1) tm = fmaxf(tm, __shfl_xor_sync(0xffffffffu, tm, o));
        float nm = fmaxf(m, tm);
        float corr = __expf(m - nm);
        float p = __expf(sc - nm);                      // 0 for masked positions
        float ps = p;
        #pragma unroll
        for (int o = 8; o; o >>= 1) ps += __shfl_xor_sync(0xffffffffu, ps, o);
        l = l*corr + ps;
        m = nm;
        {
            unsigned long long c2 = dup2(corr);
            a01a = mul2(a01a, c2); a23a = mul2(a23a, c2);
            a01b = mul2(a01b, c2); a23b = mul2(a23b, c2);
        }

        #pragma unroll 8
        for (int r = 0; r < nt; r++) {
            float pr = __shfl_sync(0xffffffffu, p, r);   // lane r holds p for position r
            unsigned long long pd = dup2(pr);
            ulonglong2 vv = *(const ulonglong2*)(&vs[bi][r][0] + 4*(lane ^ (r & 7)));
            if (r & 1) { ffma2(a01b, vv.x, pd); ffma2(a23b, vv.y, pd); }
            else       { ffma2(a01a, vv.x, pd); ffma2(a23a, vv.y, pd); }
        }
        __syncthreads();
    }

    // append the freshly-written token if it falls in this chunk
    if (last >= c0 && last < cend) {
        const float4* kn4 = (const float4*)knew;
        const float4* qp4 = (const float4*)&qs[g][0];
        float sc = 0.f;
        #pragma unroll
        for (int i = 0; i < 32; i++) {
            float4 kk = kn4[i], qq = qp4[i];
            sc += kk.x*qq.x + kk.y*qq.y + kk.z*qq.z + kk.w*qq.w;
        }
        float nm = fmaxf(m, sc);
        float corr = __expf(m - nm);
        float p = __expf(sc - nm);
        l = l*corr + p;
        m = nm;
        unsigned long long c2 = dup2(corr), pd = dup2(p);
        a01a = mul2(a01a, c2); a23a = mul2(a23a, c2);
        a01b = mul2(a01b, c2); a23b = mul2(a23b, c2);
        ulonglong2 vv = *(const ulonglong2*)(vnew + 4*lane);
        ffma2(a01a, vv.x, pd); ffma2(a23a, vv.y, pd);
    }

    if (lane == 0) { g_pm[pidx] = m; g_pl[pidx] = l; }
    {
        float2 xa = unpk(a01a), xb = unpk(a01b), ya = unpk(a23a), yb = unpk(a23b);
        float4 outp = make_float4(xa.x + xb.x, xa.y + xb.y, ya.x + yb.x, ya.y + yb.y);
        *(float4*)&g_pacc[pidx][4*lane] = outp;
    }
    #undef STAGE
}

// ---------- combine split-KV partials ----------
__global__ void __launch_bounds__(128) combine_kernel()
{
    const int kv = blockIdx.x, b = blockIdx.y;
    const int tid = threadIdx.x, lane = tid & 31, g = tid >> 5;
    const int p0 = ((b*NKV + kv)*G + g)*SPLIT;

    float M = -INFINITY;
    #pragma unroll
    for (int c = 0; c < SPLIT; c++) M = fmaxf(M, g_pm[p0 + c]);

    float L = 0.f;
    float4 o = make_float4(0.f, 0.f, 0.f, 0.f);
    #pragma unroll
    for (int c = 0; c < SPLIT; c++) {
        float pm = g_pm[p0 + c];
        float w = (pm == -INFINITY) ? 0.f : __expf(pm - M);
        L += g_pl[p0 + c] * w;
        float4 a = *(const float4*)&g_pacc[p0 + c][4*lane];
        o.x += a.x*w; o.y += a.y*w; o.z += a.z*w; o.w += a.w*w;
    }
    float inv = 1.0f / L;
    float4 r = make_float4(o.x*inv, o.y*inv, o.z*inv, o.w*inv);
    *(float4*)&g_attn[b][(kv*G + g)*HS + 4*lane] = r;
}

extern "C" void kernel_launch(void* const* d_in, const int* in_sizes, int n_in,
                              void* d_out, int out_size)
{
    const float* hs   = (const float*)d_in[0];
    const float* wq   = (const float*)d_in[1];
    const float* wk   = (const float*)d_in[2];
    const float* wv   = (const float*)d_in[3];
    const float* wo   = (const float*)d_in[4];
    const float* kc   = (const float*)d_in[5];
    const float* vc   = (const float*)d_in[6];
    const int*   bt   = (const int*)d_in[8];
    const int*   lens = (const int*)d_in[10];
    float* out = (float*)d_out;

    qkv_gemm<<<dim3(QKVN/128, KSQ), 256>>>(hs, wq, wk, wv);
    reduce_qkv<<<(B*QKVN + 255)/256, 256>>>();
    attn_kernel<<<dim3(NKV, SPLIT, B), 128>>>(kc, vc, bt, lens);
    combine_kernel<<<dim3(NKV, B), 128>>>();
    out_gemm<<<dim3(HID/128, KSO), 256>>>(wo);
    reduce_out<<<(B*HID + 255)/256, 256>>>(out);
}